// round 9
// baseline (speedup 1.0000x reference)
#include <cuda_runtime.h>

// RVOModule on GB300. B=256, N=1024, K=32.
// R9 = R8 + paired passes: two passes processed with independent register
// state, interleaved shuffle-reduction trees (kills the serial 26-cyc SHFL
// tails), prefetch of the next pair's idx/mask.

#define TAU 3.0f
#define FIX 0.2f

#define NPED 1024
#define KNEI 32
#define BPB 2                 // blocks per batch
#define THREADS 512           // peds per block

__device__ __forceinline__ float rsqrt_approx(float x) {
    float r;
    asm("rsqrt.approx.f32 %0, %1;" : "=f"(r) : "f"(x));
    return r;
}

__device__ __forceinline__ void interact(const float4 sf, const float2 vd,
                                         const float4 qv, const float m,
                                         const float thr2,
                                         float& cx, float& cy)
{
    const float rpx = sf.x - qv.x * m;
    const float rpy = sf.y - qv.y * m;
    const float rvx = vd.x - qv.z * m;
    const float rvy = vd.y - qv.w * m;

    const float dpv = rpx * rvx + rpy * rvy;
    const float dvv = rvx * rvx + rvy * rvy + 1e-6f;  // ref: +1e-6
    float t = __fdividef(dpv, dvv + 1e-6f);           // ref: second +1e-6
    t = fminf(fmaxf(t, 0.0f), TAU);

    const float dx = rpx + t * rvx;
    const float dy = rpy + t * rvy;
    const float md2 = dx * dx + dy * dy;              // min_dist^2

    const float s = rpx * rpx + rpy * rpy;            // |rel_pos|^2

    // ref: coll = (sqrt(md2)<thr) && m!=0; normal/(sqrt(s)+1e-6);
    // s==0 (self) -> numerator 0 in ref -> contributes 0.
    const bool coll = (md2 < thr2) && (m != 0.0f) && (s > 0.0f);
    const float inv = coll ? rsqrt_approx(s) : 0.0f;

    cx -= rpy * inv;
    cy += rpx * inv;
}

__global__ __launch_bounds__(THREADS, 2)
void rvo_kernel(const float2* __restrict__ p_cur,
                const float2* __restrict__ v_cur,
                const float2* __restrict__ v_desire,
                const int*    __restrict__ near_idx,
                const float*  __restrict__ neigh_mask,
                const int*    __restrict__ thr_ptr,
                float2*       __restrict__ out)
{
    __shared__ float4 pv[NPED];       // {p.x,p.y,v.x,v.y} whole batch, 16 KB
    __shared__ float2 vds[THREADS];   // v_desire for this block's peds, 4 KB

    const int b       = blockIdx.x / BPB;
    const int sub     = blockIdx.x % BPB;
    const int base    = b * NPED;
    const int pedbase = sub * THREADS;

    #pragma unroll
    for (int i = threadIdx.x; i < NPED; i += THREADS) {
        const float2 p = p_cur[base + i];
        const float2 v = v_cur[base + i];
        pv[i] = make_float4(p.x, p.y, v.x, v.y);
    }
    vds[threadIdx.x] = v_desire[base + pedbase + threadIdx.x];
    __syncthreads();

    const int warp = threadIdx.x >> 5;
    const int lane = threadIdx.x & 31;
    const int grp  = lane >> 3;            // ped (0..3) within a pass
    const int q8   = lane & 7;

    const float thrF = (float)(*thr_ptr);
    const float thr2 = thrF * thrF;

    const int nb = pedbase + warp * 32;    // within-batch id of warp's first ped
    const int g0 = base + nb;

    const int4*   idx4 = (const int4*)  (near_idx)   + (long long)g0 * (KNEI / 4) + lane;
    const float4* msk4 = (const float4*)(neigh_mask) + (long long)g0 * (KNEI / 4) + lane;

    // Prologue: passes 0 and 1.
    int4   jA = idx4[0];        float4 mA = msk4[0];
    int4   jB = idx4[32];       float4 mB = msk4[32];

    #pragma unroll 1
    for (int h = 0; h < 4; ++h) {
        const int pa = 2 * h;
        const int pb = 2 * h + 1;

        // Prefetch next pair — overlaps with both passes' compute.
        int4 jA2, jB2; float4 mA2, mB2;
        if (h < 3) {
            jA2 = idx4[(pa + 2) * 32];  mA2 = msk4[(pa + 2) * 32];
            jB2 = idx4[(pb + 2) * 32];  mB2 = msk4[(pb + 2) * 32];
        }

        const int plA = pa * 4 + grp;
        const int plB = pb * 4 + grp;
        const float4 sfA = pv[nb + plA];
        const float4 sfB = pv[nb + plB];
        const float2 vdA = vds[warp * 32 + plA];
        const float2 vdB = vds[warp * 32 + plB];

        float cxA = 0.0f, cyA = 0.0f, cxB = 0.0f, cyB = 0.0f;

        const int   jsA[4] = { jA.x, jA.y, jA.z, jA.w };
        const float msA[4] = { mA.x, mA.y, mA.z, mA.w };
        const int   jsB[4] = { jB.x, jB.y, jB.z, jB.w };
        const float msB[4] = { mB.x, mB.y, mB.z, mB.w };

        // Interleave the two passes' interactions (independent chains).
        #pragma unroll
        for (int u = 0; u < 4; ++u) {
            const float4 qA = pv[jsA[u]];
            const float4 qB = pv[jsB[u]];
            interact(sfA, vdA, qA, msA[u], thr2, cxA, cyA);
            interact(sfB, vdB, qB, msB[u], thr2, cxB, cyB);
        }

        // Interleaved reduction trees: 4 independent SHFL chains.
        #pragma unroll
        for (int o = 1; o < 8; o <<= 1) {
            cxA += __shfl_xor_sync(0xffffffffu, cxA, o);
            cxB += __shfl_xor_sync(0xffffffffu, cxB, o);
            cyA += __shfl_xor_sync(0xffffffffu, cyA, o);
            cyB += __shfl_xor_sync(0xffffffffu, cyB, o);
        }

        if (q8 == 0) {
            out[g0 + plA] = make_float2(vdA.x + cxA * FIX, vdA.y + cyA * FIX);
            out[g0 + plB] = make_float2(vdB.x + cxB * FIX, vdB.y + cyB * FIX);
        }

        jA = jA2; mA = mA2; jB = jB2; mB = mB2;
    }
}

extern "C" void kernel_launch(void* const* d_in, const int* in_sizes, int n_in,
                              void* d_out, int out_size)
{
    const float2* p_cur    = (const float2*)d_in[0];
    const float2* v_cur    = (const float2*)d_in[1];
    const float2* v_desire = (const float2*)d_in[2];
    const int*    near_idx = (const int*)d_in[3];
    const float*  mask     = (const float*)d_in[4];
    const int*    thr      = (const int*)d_in[5];
    float2*       out      = (float2*)d_out;

    const int P = in_sizes[0] / 2;          // B*N pedestrians
    const int nBatches = P / NPED;          // 256
    const int blocks = nBatches * BPB;      // 512

    rvo_kernel<<<blocks, THREADS>>>(p_cur, v_cur, v_desire, near_idx, mask, thr, out);
}

// round 10
// speedup vs baseline: 1.0097x; 1.0097x over previous
#include <cuda_runtime.h>

// RVOModule on GB300. B=256, N=1024, K=32.
// R10 = R9 + mask exploitation: neigh_ped_mask ∈ {0,1} exactly, and m==0
// contributes exactly 0. So (a) predicate the smem gather on m!=0 (halves
// LDS crossbar wavefronts), (b) drop the *m multiplies (identity for m==1),
// keeping m only in the collision predicate.

#define TAU 3.0f
#define FIX 0.2f

#define NPED 1024
#define KNEI 32
#define BPB 2                 // blocks per batch
#define THREADS 512           // peds per block

__device__ __forceinline__ float rsqrt_approx(float x) {
    float r;
    asm("rsqrt.approx.f32 %0, %1;" : "=f"(r) : "f"(x));
    return r;
}

__device__ __forceinline__ void interact(const float4 sf, const float2 vd,
                                         const float4 qv, const float m,
                                         const float thr2,
                                         float& cx, float& cy)
{
    // m ∈ {0,1}: for m==1 these equal the reference's masked forms; for m==0
    // the contribution is forced to 0 by the coll predicate below.
    const float rpx = sf.x - qv.x;
    const float rpy = sf.y - qv.y;
    const float rvx = vd.x - qv.z;
    const float rvy = vd.y - qv.w;

    const float dpv = rpx * rvx + rpy * rvy;
    const float dvv = rvx * rvx + rvy * rvy + 1e-6f;  // ref: +1e-6
    float t = __fdividef(dpv, dvv + 1e-6f);           // ref: second +1e-6
    t = fminf(fmaxf(t, 0.0f), TAU);

    const float dx = rpx + t * rvx;
    const float dy = rpy + t * rvy;
    const float md2 = dx * dx + dy * dy;              // min_dist^2

    const float s = rpx * rpx + rpy * rpy;            // |rel_pos|^2

    // ref: coll = (sqrt(md2)<thr) && m!=0; normal/(sqrt(s)+1e-6);
    // s==0 (self, m==1) -> numerator 0 in ref -> contributes 0.
    const bool coll = (md2 < thr2) && (m != 0.0f) && (s > 0.0f);
    const float inv = coll ? rsqrt_approx(s) : 0.0f;

    cx -= rpy * inv;
    cy += rpx * inv;
}

__global__ __launch_bounds__(THREADS, 2)
void rvo_kernel(const float2* __restrict__ p_cur,
                const float2* __restrict__ v_cur,
                const float2* __restrict__ v_desire,
                const int*    __restrict__ near_idx,
                const float*  __restrict__ neigh_mask,
                const int*    __restrict__ thr_ptr,
                float2*       __restrict__ out)
{
    __shared__ float4 pv[NPED];       // {p.x,p.y,v.x,v.y} whole batch, 16 KB
    __shared__ float2 vds[THREADS];   // v_desire for this block's peds, 4 KB

    const int b       = blockIdx.x / BPB;
    const int sub     = blockIdx.x % BPB;
    const int base    = b * NPED;
    const int pedbase = sub * THREADS;

    #pragma unroll
    for (int i = threadIdx.x; i < NPED; i += THREADS) {
        const float2 p = p_cur[base + i];
        const float2 v = v_cur[base + i];
        pv[i] = make_float4(p.x, p.y, v.x, v.y);
    }
    vds[threadIdx.x] = v_desire[base + pedbase + threadIdx.x];
    __syncthreads();

    const int warp = threadIdx.x >> 5;
    const int lane = threadIdx.x & 31;
    const int grp  = lane >> 3;            // ped (0..3) within a pass
    const int q8   = lane & 7;

    const float thrF = (float)(*thr_ptr);
    const float thr2 = thrF * thrF;

    const int nb = pedbase + warp * 32;    // within-batch id of warp's first ped
    const int g0 = base + nb;

    const int4*   idx4 = (const int4*)  (near_idx)   + (long long)g0 * (KNEI / 4) + lane;
    const float4* msk4 = (const float4*)(neigh_mask) + (long long)g0 * (KNEI / 4) + lane;

    // Prologue: passes 0 and 1.
    int4   jA = idx4[0];        float4 mA = msk4[0];
    int4   jB = idx4[32];       float4 mB = msk4[32];

    #pragma unroll 1
    for (int h = 0; h < 4; ++h) {
        const int pa = 2 * h;
        const int pb = 2 * h + 1;

        // Prefetch next pair — overlaps with both passes' compute.
        int4 jA2, jB2; float4 mA2, mB2;
        if (h < 3) {
            jA2 = idx4[(pa + 2) * 32];  mA2 = msk4[(pa + 2) * 32];
            jB2 = idx4[(pb + 2) * 32];  mB2 = msk4[(pb + 2) * 32];
        }

        const int plA = pa * 4 + grp;
        const int plB = pb * 4 + grp;
        const float4 sfA = pv[nb + plA];
        const float4 sfB = pv[nb + plB];
        const float2 vdA = vds[warp * 32 + plA];
        const float2 vdB = vds[warp * 32 + plB];

        float cxA = 0.0f, cyA = 0.0f, cxB = 0.0f, cyB = 0.0f;

        const int   jsA[4] = { jA.x, jA.y, jA.z, jA.w };
        const float msA[4] = { mA.x, mA.y, mA.z, mA.w };
        const int   jsB[4] = { jB.x, jB.y, jB.z, jB.w };
        const float msB[4] = { mB.x, mB.y, mB.z, mB.w };

        #pragma unroll
        for (int u = 0; u < 4; ++u) {
            // Predicated gathers: lanes with m==0 skip the LDS entirely
            // (no crossbar bank accesses), contribution is exactly 0.
            float4 qA = make_float4(0.f, 0.f, 0.f, 0.f);
            float4 qB = make_float4(0.f, 0.f, 0.f, 0.f);
            if (msA[u] != 0.0f) qA = pv[jsA[u]];
            if (msB[u] != 0.0f) qB = pv[jsB[u]];
            interact(sfA, vdA, qA, msA[u], thr2, cxA, cyA);
            interact(sfB, vdB, qB, msB[u], thr2, cxB, cyB);
        }

        // Interleaved reduction trees: 4 independent SHFL chains.
        #pragma unroll
        for (int o = 1; o < 8; o <<= 1) {
            cxA += __shfl_xor_sync(0xffffffffu, cxA, o);
            cxB += __shfl_xor_sync(0xffffffffu, cxB, o);
            cyA += __shfl_xor_sync(0xffffffffu, cyA, o);
            cyB += __shfl_xor_sync(0xffffffffu, cyB, o);
        }

        if (q8 == 0) {
            out[g0 + plA] = make_float2(vdA.x + cxA * FIX, vdA.y + cyA * FIX);
            out[g0 + plB] = make_float2(vdB.x + cxB * FIX, vdB.y + cyB * FIX);
        }

        jA = jA2; mA = mA2; jB = jB2; mB = mB2;
    }
}

extern "C" void kernel_launch(void* const* d_in, const int* in_sizes, int n_in,
                              void* d_out, int out_size)
{
    const float2* p_cur    = (const float2*)d_in[0];
    const float2* v_cur    = (const float2*)d_in[1];
    const float2* v_desire = (const float2*)d_in[2];
    const int*    near_idx = (const int*)d_in[3];
    const float*  mask     = (const float*)d_in[4];
    const int*    thr      = (const int*)d_in[5];
    float2*       out      = (float2*)d_out;

    const int P = in_sizes[0] / 2;          // B*N pedestrians
    const int nBatches = P / NPED;          // 256
    const int blocks = nBatches * BPB;      // 512

    rvo_kernel<<<blocks, THREADS>>>(p_cur, v_cur, v_desire, near_idx, mask, thr, out);
}

// round 11
// speedup vs baseline: 1.1082x; 1.0976x over previous
#include <cuda_runtime.h>

// RVOModule on GB300. B=256, N=1024, K=32.
// R11 = R10 + instruction-stream slimming:
//  - dvv epsilon folded: +2e-6 inside the fma chain
//  - coll test md2 < thr2*m  (m in {0,1}; md2>=0 so m=0 -> always false)
//  - s>0 guard replaced by rsqrt(max(s,1e-30)) (s==0 => rp==0 => contrib 0)
//  - persistent gather registers (predicated LDS keeps stale finite values;
//    garbage is discarded by the m=0 coll test)

#define TAU 3.0f
#define FIX 0.2f

#define NPED 1024
#define KNEI 32
#define BPB 2                 // blocks per batch
#define THREADS 512           // peds per block

__device__ __forceinline__ float rsqrt_approx(float x) {
    float r;
    asm("rsqrt.approx.f32 %0, %1;" : "=f"(r) : "f"(x));
    return r;
}

__device__ __forceinline__ void interact(const float4 sf, const float2 vd,
                                         const float4 qv, const float thr2m,
                                         float& cx, float& cy)
{
    const float rpx = sf.x - qv.x;
    const float rpy = sf.y - qv.y;
    const float rvx = vd.x - qv.z;
    const float rvy = vd.y - qv.w;

    const float dpv = fmaf(rpx, rvx, rpy * rvy);
    // ref: (sum + 1e-6) + 1e-6  ==  sum + 2e-6 (to <1 ulp)
    const float dvv = fmaf(rvx, rvx, fmaf(rvy, rvy, 2e-6f));
    float t = __fdividef(dpv, dvv);
    t = fminf(fmaxf(t, 0.0f), TAU);

    const float dx = fmaf(t, rvx, rpx);
    const float dy = fmaf(t, rvy, rpy);
    const float md2 = fmaf(dx, dx, dy * dy);      // min_dist^2
    const float s   = fmaf(rpx, rpx, rpy * rpy);  // |rel_pos|^2

    // thr2m = thr^2 * m: m==0 -> 0, md2 < 0 never true -> contrib 0 (matches ref).
    // s==0 (self, m==1): rp==0 -> contrib = 0 * big = 0 (matches ref).
    const float inv = (md2 < thr2m) ? rsqrt_approx(fmaxf(s, 1e-30f)) : 0.0f;

    cx -= rpy * inv;
    cy += rpx * inv;
}

__global__ __launch_bounds__(THREADS, 2)
void rvo_kernel(const float2* __restrict__ p_cur,
                const float2* __restrict__ v_cur,
                const float2* __restrict__ v_desire,
                const int*    __restrict__ near_idx,
                const float*  __restrict__ neigh_mask,
                const int*    __restrict__ thr_ptr,
                float2*       __restrict__ out)
{
    __shared__ float4 pv[NPED];       // {p.x,p.y,v.x,v.y} whole batch, 16 KB
    __shared__ float2 vds[THREADS];   // v_desire for this block's peds, 4 KB

    const int b       = blockIdx.x / BPB;
    const int sub     = blockIdx.x % BPB;
    const int base    = b * NPED;
    const int pedbase = sub * THREADS;

    #pragma unroll
    for (int i = threadIdx.x; i < NPED; i += THREADS) {
        const float2 p = p_cur[base + i];
        const float2 v = v_cur[base + i];
        pv[i] = make_float4(p.x, p.y, v.x, v.y);
    }
    vds[threadIdx.x] = v_desire[base + pedbase + threadIdx.x];
    __syncthreads();

    const int warp = threadIdx.x >> 5;
    const int lane = threadIdx.x & 31;
    const int grp  = lane >> 3;            // ped (0..3) within a pass
    const int q8   = lane & 7;

    const float thrF = (float)(*thr_ptr);
    const float thr2 = thrF * thrF;

    const int nb = pedbase + warp * 32;    // within-batch id of warp's first ped
    const int g0 = base + nb;

    const int4*   idx4 = (const int4*)  (near_idx)   + (long long)g0 * (KNEI / 4) + lane;
    const float4* msk4 = (const float4*)(neigh_mask) + (long long)g0 * (KNEI / 4) + lane;

    // Prologue: passes 0 and 1.
    int4   jA = idx4[0];        float4 mA = msk4[0];
    int4   jB = idx4[32];       float4 mB = msk4[32];

    // Persistent gather registers: predicated loads keep stale finite values;
    // the m==0 coll test discards any garbage math.
    float4 qA = make_float4(0.f, 0.f, 0.f, 0.f);
    float4 qB = make_float4(0.f, 0.f, 0.f, 0.f);

    #pragma unroll 1
    for (int h = 0; h < 4; ++h) {
        const int pa = 2 * h;
        const int pb = 2 * h + 1;

        // Prefetch next pair — overlaps with both passes' compute.
        int4 jA2, jB2; float4 mA2, mB2;
        if (h < 3) {
            jA2 = idx4[(pa + 2) * 32];  mA2 = msk4[(pa + 2) * 32];
            jB2 = idx4[(pb + 2) * 32];  mB2 = msk4[(pb + 2) * 32];
        }

        const int plA = pa * 4 + grp;
        const int plB = pb * 4 + grp;
        const float4 sfA = pv[nb + plA];
        const float4 sfB = pv[nb + plB];
        const float2 vdA = vds[warp * 32 + plA];
        const float2 vdB = vds[warp * 32 + plB];

        float cxA = 0.0f, cyA = 0.0f, cxB = 0.0f, cyB = 0.0f;

        const int   jsA[4] = { jA.x, jA.y, jA.z, jA.w };
        const float msA[4] = { mA.x, mA.y, mA.z, mA.w };
        const int   jsB[4] = { jB.x, jB.y, jB.z, jB.w };
        const float msB[4] = { mB.x, mB.y, mB.z, mB.w };

        #pragma unroll
        for (int u = 0; u < 4; ++u) {
            // Predicated gathers: lanes with m==0 skip the LDS entirely.
            if (msA[u] != 0.0f) qA = pv[jsA[u]];
            if (msB[u] != 0.0f) qB = pv[jsB[u]];
            interact(sfA, vdA, qA, thr2 * msA[u], cxA, cyA);
            interact(sfB, vdB, qB, thr2 * msB[u], cxB, cyB);
        }

        // Interleaved reduction trees: 4 independent SHFL chains.
        #pragma unroll
        for (int o = 1; o < 8; o <<= 1) {
            cxA += __shfl_xor_sync(0xffffffffu, cxA, o);
            cxB += __shfl_xor_sync(0xffffffffu, cxB, o);
            cyA += __shfl_xor_sync(0xffffffffu, cyA, o);
            cyB += __shfl_xor_sync(0xffffffffu, cyB, o);
        }

        if (q8 == 0) {
            out[g0 + plA] = make_float2(vdA.x + cxA * FIX, vdA.y + cyA * FIX);
            out[g0 + plB] = make_float2(vdB.x + cxB * FIX, vdB.y + cyB * FIX);
        }

        jA = jA2; mA = mA2; jB = jB2; mB = mB2;
    }
}

extern "C" void kernel_launch(void* const* d_in, const int* in_sizes, int n_in,
                              void* d_out, int out_size)
{
    const float2* p_cur    = (const float2*)d_in[0];
    const float2* v_cur    = (const float2*)d_in[1];
    const float2* v_desire = (const float2*)d_in[2];
    const int*    near_idx = (const int*)d_in[3];
    const float*  mask     = (const float*)d_in[4];
    const int*    thr      = (const int*)d_in[5];
    float2*       out      = (float2*)d_out;

    const int P = in_sizes[0] / 2;          // B*N pedestrians
    const int nBatches = P / NPED;          // 256
    const int blocks = nBatches * BPB;      // 512

    rvo_kernel<<<blocks, THREADS>>>(p_cur, v_cur, v_desire, near_idx, mask, thr, out);
}